// round 5
// baseline (speedup 1.0000x reference)
#include <cuda_runtime.h>
#include <math.h>

#define MDL   4
#define CDIM  1000
#define NV4   250          // CDIM/4 float4 per row
#define NTHR  128          // 4 warps: warp m handles model m
#define LOGC  6.90775527898213705f   // log(1000)
#define GRID  1184         // 8 * 148 SMs, persistent grid-stride blocks

// Device globals (no allocation). Zero-init at load; last block restores
// zeros every launch -> deterministic graph replays.
__device__ double   g_acc[2];
__device__ unsigned g_count;

__device__ __forceinline__ const float4* row_ptr(
    const float* logits, int warp, int b, int B)
{
    return (const float4*)(logits + ((size_t)warp * (size_t)B + (size_t)b) * CDIM);
}

__device__ __forceinline__ void load_row(
    float4* __restrict__ buf, const float4* __restrict__ row, int lane)
{
    #pragma unroll
    for (int k = 0; k < 8; k++) {
        int i = lane + 32 * k;
        if (i < NV4) buf[k] = __ldg(row + i);
    }
}

__device__ __forceinline__ void process_sample(
    int b, const float4* __restrict__ buf,
    const float* __restrict__ logits, const int* __restrict__ t32,
    int is64, int B,
    float* __restrict__ oracle, float* __restrict__ idx_out,
    double& acc0, double& acc1,
    float* s_score, float* s_ent, int* s_win,
    int warp, int lane)
{
    // Winner score (ce - ent) = mean(x) - x_t + logC: the logsumexp cancels
    // analytically, so the argmin (and the oracle rows it selects) is exp-free
    // and exact in fp32. __expf error only touches the scalar loss (tol 1e-3).
    float ssum = 0.0f, sexp = 0.0f;
    #pragma unroll
    for (int k = 0; k < 8; k++) {
        int i = lane + 32 * k;
        if (i < NV4) {
            float4 v = buf[k];
            ssum += (v.x + v.y) + (v.z + v.w);
            sexp += (__expf(v.x) + __expf(v.y)) + (__expf(v.z) + __expf(v.w));
        }
    }
    #pragma unroll
    for (int off = 16; off > 0; off >>= 1) {
        ssum += __shfl_xor_sync(0xFFFFFFFFu, ssum, off);
        sexp += __shfl_xor_sync(0xFFFFFFFFu, sexp, off);
    }

    if (lane == 0) {
        int tgt = is64 ? t32[2 * b] : t32[b];
        const float* row_f = (const float*)row_ptr(logits, warp, b, B);
        float tval = __ldg(row_f + tgt);           // L1-hot (row just streamed)
        float mean = ssum * (1.0f / CDIM);
        s_score[warp] = mean - tval;               // ce - ent - logC
        s_ent[warp]   = logf(sexp) - mean - LOGC;  // entropy term
    }
    __syncthreads();

    if (threadIdx.x == 0) {
        // argmin_m (ce - ent); strict <: first-min wins (jax tie-break).
        float best = s_score[0];
        int   win  = 0;
        float entsum = s_ent[0];
        #pragma unroll
        for (int m = 1; m < MDL; m++) {
            entsum += s_ent[m];
            if (s_score[m] < best) { best = s_score[m]; win = m; }
        }
        *s_win = win;
        if (idx_out) idx_out[b] = (float)win;
        acc0 += (double)(best + LOGC);             // ce_win - ent_win
        acc1 += (double)entsum;
    }
    __syncthreads();

    // Oracle row copy; source L1-hot from the winning warp's streaming reads.
    if (oracle) {
        const float* __restrict__ src =
            (const float*)row_ptr(logits, *s_win, b, B);
        float* __restrict__ dst = oracle + (size_t)b * CDIM;  // 4B-aligned
        for (int i = threadIdx.x; i < CDIM; i += NTHR)
            dst[i] = __ldg(src + i);
    }
}

__global__ __launch_bounds__(NTHR) void cmcl_fused(
    const float* __restrict__ logits,        // (M, B, C) fp32
    const int*   __restrict__ t32,           // targets viewed as int32 words
    float* __restrict__ loss_out,            // scalar or null
    float* __restrict__ oracle,              // (B, C) or null
    float* __restrict__ idx_out,             // (B,)  or null
    int B)
{
    const int warp = threadIdx.x >> 5;       // model index m
    const int lane = threadIdx.x & 31;

    __shared__ float s_score[MDL];
    __shared__ float s_ent[MDL];
    __shared__ int   s_win;
    __shared__ int   s_is64;

    if (threadIdx.x == 0) {
        // int64 vs int32 targets: true int64 (<1000, LE) has zero odd words;
        // 16 random int32 words matching that: p ~ 1e-48.
        int is64 = 1;
        #pragma unroll
        for (int k = 0; k < 16; k++)
            if (t32[2 * k + 1] != 0) { is64 = 0; break; }
        s_is64 = is64;
    }
    __syncthreads();
    const int is64 = s_is64;

    double acc0 = 0.0, acc1 = 0.0;           // thread 0's block-partial sums
    const int stride = gridDim.x;

    // Grid-stride with software double-buffering: sample n+1's loads are in
    // flight while sample n is processed.
    float4 bufA[8], bufB[8];
    int b = blockIdx.x;
    if (b < B) load_row(bufA, row_ptr(logits, warp, b, B), lane);
    while (b < B) {
        int b2 = b + stride;
        if (b2 < B) load_row(bufB, row_ptr(logits, warp, b2, B), lane);
        process_sample(b, bufA, logits, t32, is64, B, oracle, idx_out,
                       acc0, acc1, s_score, s_ent, &s_win, warp, lane);
        int b3 = b2 + stride;
        if (b3 < B) load_row(bufA, row_ptr(logits, warp, b3, B), lane);
        if (b2 < B)
            process_sample(b2, bufB, logits, t32, is64, B, oracle, idx_out,
                           acc0, acc1, s_score, s_ent, &s_win, warp, lane);
        b = b3;
    }

    // Block tail: one atomic pair + one fence + one counter bump per block.
    if (threadIdx.x == 0) {
        atomicAdd(&g_acc[0], acc0);
        atomicAdd(&g_acc[1], acc1);
        __threadfence();
        unsigned t = atomicAdd(&g_count, 1u);
        if (t == (unsigned)gridDim.x - 1u) {
            double a0 = __longlong_as_double(
                atomicExch((unsigned long long*)&g_acc[0], 0ull));
            double a1 = __longlong_as_double(
                atomicExch((unsigned long long*)&g_acc[1], 0ull));
            if (loss_out) loss_out[0] = (float)((a0 + a1) / (double)B);
            g_count = 0u;          // reset for next graph replay
            __threadfence();
        }
    }
}

extern "C" void kernel_launch(void* const* d_in, const int* in_sizes, int n_in,
                              void* d_out, int out_size)
{
    const float* logits = (const float*)d_in[0];
    const int*   t32    = (const int*)d_in[1];
    const int B = in_sizes[1];                 // 8192

    float* out = (float*)d_out;
    const long long bc = (long long)B * CDIM;

    // Output layout: tuple (new_loss, oracle_logits, min_index) flattened.
    float* loss_p   = nullptr;
    float* oracle_p = nullptr;
    float* idx_p    = nullptr;
    long long osz = (long long)out_size;
    if (osz >= 1 + bc + B) {                   // full tuple
        loss_p   = out;
        oracle_p = out + 1;
        idx_p    = out + 1 + bc;
    } else if (osz == bc + B) {                // (oracle, idx)
        oracle_p = out;
        idx_p    = out + bc;
    } else if (osz == bc) {                    // oracle only
        oracle_p = out;
    } else if (osz == B) {                     // idx only
        idx_p = out;
    } else {                                   // scalar loss only
        loss_p = out;
    }

    cmcl_fused<<<GRID, NTHR>>>(logits, t32, loss_p, oracle_p, idx_p, B);
}

// round 6
// speedup vs baseline: 1.1420x; 1.1420x over previous
#include <cuda_runtime.h>
#include <math.h>
#include <stdint.h>

#define MDL    4
#define CDIM   1000
#define NV4    250                      // CDIM/4 float4 per row
#define NTHR   128                      // 4 warps: warp m handles model m
#define LOGC   6.90775527898213705f    // log(1000)
#define NSTAGE 6                        // smem pipeline depth
#define ROWB   4096                     // bytes per row slot (1000 floats, padded)
#define SLOTB  (MDL * ROWB)             // 16384 B per stage (4 rows)
#define SLOTTX (MDL * CDIM * 4)         // 16000 B actually transferred per stage
#define GRIDB  296                      // 2 blocks per SM, persistent single wave

// Device globals (no allocation). Zero-init at load; last block restores zeros
// every launch -> deterministic graph replays.
__device__ double   g_acc[2];
__device__ unsigned g_count;

__device__ __forceinline__ uint32_t smem_u32(const void* p) {
    uint32_t a;
    asm("{ .reg .u64 t; cvta.to.shared.u64 t, %1; cvt.u32.u64 %0, t; }"
        : "=r"(a) : "l"(p));
    return a;
}

__device__ __forceinline__ void mbar_init(uint32_t mbar, uint32_t cnt) {
    asm volatile("mbarrier.init.shared.b64 [%0], %1;" :: "r"(mbar), "r"(cnt) : "memory");
}
__device__ __forceinline__ void mbar_expect_tx(uint32_t mbar, uint32_t bytes) {
    asm volatile("mbarrier.arrive.expect_tx.shared.b64 _, [%0], %1;"
                 :: "r"(mbar), "r"(bytes) : "memory");
}
__device__ __forceinline__ void mbar_wait(uint32_t mbar, uint32_t parity) {
    uint32_t done;
    asm volatile(
        "{\n\t.reg .pred p;\n\t"
        "mbarrier.try_wait.parity.acquire.cta.shared::cta.b64 p, [%1], %2;\n\t"
        "selp.b32 %0, 1, 0, p;\n\t}"
        : "=r"(done) : "r"(mbar), "r"(parity) : "memory");
    if (!done) {
        asm volatile(
            "{\n\t.reg .pred P1;\n\t"
            "WL_%=:\n\t"
            "mbarrier.try_wait.parity.acquire.cta.shared::cta.b64 P1, [%0], %1, 0x989680;\n\t"
            "@P1 bra.uni WD_%=;\n\t"
            "bra.uni WL_%=;\n\t"
            "WD_%=:\n\t}"
            :: "r"(mbar), "r"(parity) : "memory");
    }
}
// 1D bulk async copy global -> shared, completion via mbarrier tx bytes.
__device__ __forceinline__ void bulk_g2s(uint32_t dst, const void* src,
                                         uint32_t bytes, uint32_t mbar) {
    asm volatile(
        "cp.async.bulk.shared::cluster.global.mbarrier::complete_tx::bytes "
        "[%0], [%1], %2, [%3];"
        :: "r"(dst), "l"(src), "r"(bytes), "r"(mbar) : "memory");
}

extern __shared__ char stage_mem[];     // NSTAGE * SLOTB bytes, 16B aligned

__global__ __launch_bounds__(NTHR) void cmcl_pipe(
    const float* __restrict__ logits,   // (M, B, C) fp32
    const int*   __restrict__ t32,      // targets viewed as int32 words
    float* __restrict__ loss_out,       // scalar or null
    float* __restrict__ oracle,         // (B, C) or null
    float* __restrict__ idx_out,        // (B,)  or null
    int B, int q, int oalign)
{
    __shared__ float s_score[MDL];
    __shared__ float s_ent[MDL];
    __shared__ int   s_is64;
    __shared__ alignas(8) unsigned long long s_mbar[NSTAGE];

    const int tid  = threadIdx.x;
    const int warp = tid >> 5;          // model index m
    const int lane = tid & 31;

    const int base = blockIdx.x * q;
    int ns = B - base;
    if (ns > q) ns = q;
    if (ns < 0) ns = 0;

    double acc0 = 0.0, acc1 = 0.0;      // thread 0's block-partial sums

    if (ns > 0) {
        if (tid == 0) {
            // int64 vs int32 targets: true int64 (<1000, LE) has zero odd
            // words; 16 random int32 words matching that: p ~ 1e-48.
            int is64 = 1;
            #pragma unroll
            for (int k = 0; k < 16; k++)
                if (t32[2 * k + 1] != 0) { is64 = 0; break; }
            s_is64 = is64;
            #pragma unroll
            for (int s = 0; s < NSTAGE; s++)
                mbar_init(smem_u32(&s_mbar[s]), 1);
        }
        __syncthreads();
        const int is64   = s_is64;
        const uint32_t smem0 = smem_u32(stage_mem);

        // Prologue: fill the pipeline.
        if (tid == 0) {
            int pre = ns < NSTAGE ? ns : NSTAGE;
            for (int n = 0; n < pre; n++) {
                uint32_t mb = smem_u32(&s_mbar[n]);
                mbar_expect_tx(mb, SLOTTX);
                #pragma unroll
                for (int mm = 0; mm < MDL; mm++)
                    bulk_g2s(smem0 + n * SLOTB + mm * ROWB,
                             logits + ((size_t)mm * B + base + n) * CDIM,
                             CDIM * 4, mb);
            }
        }

        for (int n = 0; n < ns; n++) {
            const int s  = n % NSTAGE;
            const int ph = (n / NSTAGE) & 1;
            mbar_wait(smem_u32(&s_mbar[s]), ph);

            const int b = base + n;
            const char* slot = stage_mem + s * SLOTB;
            const float4* __restrict__ row = (const float4*)(slot + warp * ROWB);

            // Winner score (ce - ent) = mean(x) - x_t + logC: logsumexp cancels
            // analytically, so the argmin (and oracle rows) is exp-free and
            // exact in fp32. __expf error only touches the scalar loss.
            float ssum = 0.0f, sexp = 0.0f;
            #pragma unroll
            for (int k = 0; k < 8; k++) {
                int i = lane + 32 * k;
                if (i < NV4) {
                    float4 v = row[i];
                    ssum += (v.x + v.y) + (v.z + v.w);
                    sexp += (__expf(v.x) + __expf(v.y))
                          + (__expf(v.z) + __expf(v.w));
                }
            }
            #pragma unroll
            for (int off = 16; off > 0; off >>= 1) {
                ssum += __shfl_xor_sync(0xFFFFFFFFu, ssum, off);
                sexp += __shfl_xor_sync(0xFFFFFFFFu, sexp, off);
            }

            if (lane == 0) {
                int tgt    = is64 ? t32[2 * b] : t32[b];
                float tval = ((const float*)row)[tgt];       // smem
                float mean = ssum * (1.0f / CDIM);
                s_score[warp] = mean - tval;                 // ce - ent - logC
                s_ent[warp]   = logf(sexp) - mean - LOGC;
            }
            __syncthreads();

            // All threads compute the argmin redundantly (deterministic).
            // Strict <: first-min wins (jax argmin tie-break).
            float best = s_score[0];
            int   win  = 0;
            #pragma unroll
            for (int m = 1; m < MDL; m++)
                if (s_score[m] < best) { best = s_score[m]; win = m; }

            if (tid == 0) {
                if (idx_out) idx_out[b] = (float)win;
                acc0 += (double)(best + LOGC);               // ce_win - ent_win
                acc1 += (double)(s_ent[0] + s_ent[1] + s_ent[2] + s_ent[3]);
            }

            // Oracle row copy straight from smem (no global re-read).
            if (oracle) {
                const char* srcp = slot + win * ROWB;
                float* __restrict__ dst = oracle + (size_t)b * CDIM;
                if (oalign) {
                    const float4* s4 = (const float4*)srcp;
                    for (int i = tid; i < NV4; i += NTHR)
                        ((float4*)dst)[i] = s4[i];
                } else {
                    const float* sf = (const float*)srcp;
                    for (int i = tid; i < CDIM; i += NTHR)
                        dst[i] = sf[i];
                }
            }
            __syncthreads();            // all reads of slot s done

            // Refill slot s with sample n + NSTAGE.
            if (tid == 0) {
                int m = n + NSTAGE;
                if (m < ns) {
                    uint32_t mb = smem_u32(&s_mbar[s]);
                    mbar_expect_tx(mb, SLOTTX);
                    #pragma unroll
                    for (int mm = 0; mm < MDL; mm++)
                        bulk_g2s(smem0 + s * SLOTB + mm * ROWB,
                                 logits + ((size_t)mm * B + base + m) * CDIM,
                                 CDIM * 4, mb);
                }
            }
        }
    }

    // Block tail: one atomic pair + counter; last block finalizes and resets.
    if (tid == 0) {
        atomicAdd(&g_acc[0], acc0);
        atomicAdd(&g_acc[1], acc1);
        __threadfence();
        unsigned t = atomicAdd(&g_count, 1u);
        if (t == (unsigned)gridDim.x - 1u) {
            double a0 = __longlong_as_double(
                atomicExch((unsigned long long*)&g_acc[0], 0ull));
            double a1 = __longlong_as_double(
                atomicExch((unsigned long long*)&g_acc[1], 0ull));
            if (loss_out) loss_out[0] = (float)((a0 + a1) / (double)B);
            g_count = 0u;
            __threadfence();
        }
    }
}

extern "C" void kernel_launch(void* const* d_in, const int* in_sizes, int n_in,
                              void* d_out, int out_size)
{
    const float* logits = (const float*)d_in[0];
    const int*   t32    = (const int*)d_in[1];
    const int B = in_sizes[1];                 // 8192

    float* out = (float*)d_out;
    const long long bc = (long long)B * CDIM;

    // Output layout: tuple (new_loss, oracle_logits, min_index) flattened.
    float* loss_p   = nullptr;
    float* oracle_p = nullptr;
    float* idx_p    = nullptr;
    long long osz = (long long)out_size;
    if (osz >= 1 + bc + B) {                   // full tuple
        loss_p   = out;
        oracle_p = out + 1;
        idx_p    = out + 1 + bc;
    } else if (osz == bc + B) {                // (oracle, idx)
        oracle_p = out;
        idx_p    = out + bc;
    } else if (osz == bc) {                    // oracle only
        oracle_p = out;
    } else if (osz == B) {                     // idx only
        idx_p = out;
    } else {                                   // scalar loss only
        loss_p = out;
    }

    const int q = (B + GRIDB - 1) / GRIDB;     // samples per block (contiguous)
    const int oalign = (((uintptr_t)oracle_p) & 15) == 0 ? 1 : 0;
    const int dyn = NSTAGE * SLOTB;            // 96 KB

    cudaFuncSetAttribute(cmcl_pipe,
                         cudaFuncAttributeMaxDynamicSharedMemorySize, dyn);
    cmcl_pipe<<<GRIDB, NTHR, dyn>>>(logits, t32, loss_p, oracle_p, idx_p,
                                    B, q, oalign);
}

// round 7
// speedup vs baseline: 1.3381x; 1.1718x over previous
#include <cuda_runtime.h>
#include <math.h>
#include <stdint.h>

#define MDL    4
#define CDIM   1000
#define NV4    250                      // CDIM/4 float4 per row
#define NTHR   256                      // 8 warps: (sample 0/1) x (model 0..3)
#define LOGC   6.90775527898213705f    // log(1000)
#define NSTAGE 3                        // smem pipeline depth
#define ROWB   4096                     // bytes per row (1000 floats, padded)
#define SPS    2                        // samples per stage
#define SLOTB  (SPS * MDL * ROWB)       // 32 KB per stage
#define ROWTX  (CDIM * 4)               // 4000 B per row transfer
#define GRIDB  296                      // 2 blocks/SM, persistent single wave

// Device globals (no allocation). Zero-init at load; last block restores zeros
// every launch -> deterministic graph replays.
__device__ double   g_acc[2];
__device__ unsigned g_count;

__device__ __forceinline__ uint32_t smem_u32(const void* p) {
    uint32_t a;
    asm("{ .reg .u64 t; cvta.to.shared.u64 t, %1; cvt.u32.u64 %0, t; }"
        : "=r"(a) : "l"(p));
    return a;
}
__device__ __forceinline__ void mbar_init(uint32_t mbar, uint32_t cnt) {
    asm volatile("mbarrier.init.shared.b64 [%0], %1;" :: "r"(mbar), "r"(cnt) : "memory");
}
__device__ __forceinline__ void mbar_expect_tx(uint32_t mbar, uint32_t bytes) {
    asm volatile("mbarrier.arrive.expect_tx.shared.b64 _, [%0], %1;"
                 :: "r"(mbar), "r"(bytes) : "memory");
}
__device__ __forceinline__ void mbar_wait(uint32_t mbar, uint32_t parity) {
    uint32_t done;
    asm volatile(
        "{\n\t.reg .pred p;\n\t"
        "mbarrier.try_wait.parity.acquire.cta.shared::cta.b64 p, [%1], %2;\n\t"
        "selp.b32 %0, 1, 0, p;\n\t}"
        : "=r"(done) : "r"(mbar), "r"(parity) : "memory");
    if (!done) {
        asm volatile(
            "{\n\t.reg .pred P1;\n\t"
            "WL_%=:\n\t"
            "mbarrier.try_wait.parity.acquire.cta.shared::cta.b64 P1, [%0], %1, 0x989680;\n\t"
            "@P1 bra.uni WD_%=;\n\t"
            "bra.uni WL_%=;\n\t"
            "WD_%=:\n\t}"
            :: "r"(mbar), "r"(parity) : "memory");
    }
}
__device__ __forceinline__ void bulk_g2s(uint32_t dst, const void* src,
                                         uint32_t bytes, uint32_t mbar) {
    asm volatile(
        "cp.async.bulk.shared::cluster.global.mbarrier::complete_tx::bytes "
        "[%0], [%1], %2, [%3];"
        :: "r"(dst), "l"(src), "r"(bytes), "r"(mbar) : "memory");
}

extern __shared__ char stage_mem[];     // NSTAGE * SLOTB, 16B aligned

__global__ __launch_bounds__(NTHR) void cmcl_pipe2(
    const float* __restrict__ logits,   // (M, B, C) fp32
    const int*   __restrict__ t32,      // targets viewed as int32 words
    float* __restrict__ loss_out,       // scalar or null
    float* __restrict__ oracle,         // (B, C) or null
    float* __restrict__ idx_out,        // (B,)  or null
    int B, int q)
{
    __shared__ float s_score[SPS][MDL];
    __shared__ float s_ent[SPS][MDL];
    __shared__ int   s_is64;
    __shared__ alignas(8) unsigned long long s_mbar[NSTAGE];

    const int tid  = threadIdx.x;
    const int warp = tid >> 5;
    const int lane = tid & 31;
    const int samp = warp >> 2;         // 0 or 1: sample within stage
    const int mdl  = warp & 3;          // model index

    const int base = blockIdx.x * q;
    int ns = B - base;
    if (ns > q) ns = q;
    if (ns < 0) ns = 0;

    double acc0 = 0.0, acc1 = 0.0;      // thread 0's block-partial sums

    if (ns > 0) {
        if (tid == 0) {
            // int64 vs int32 targets: true int64 (<1000, LE) has zero odd
            // words; 16 random int32 words matching that: p ~ 1e-48.
            int is64 = 1;
            #pragma unroll
            for (int k = 0; k < 16; k++)
                if (t32[2 * k + 1] != 0) { is64 = 0; break; }
            s_is64 = is64;
            #pragma unroll
            for (int s = 0; s < NSTAGE; s++)
                mbar_init(smem_u32(&s_mbar[s]), 1);
        }
        __syncthreads();
        const int is64 = s_is64;
        const uint32_t smem0 = smem_u32(stage_mem);

        const int NI = (ns + SPS - 1) / SPS;     // stage iterations

        // Fill stage `s` with samples base + SPS*it .. (cnt rows x models).
        auto fill = [&](int s, int it) {
            int n0  = SPS * it;
            int cnt = ns - n0; if (cnt > SPS) cnt = SPS;
            uint32_t mb = smem_u32(&s_mbar[s]);
            mbar_expect_tx(mb, (uint32_t)(cnt * MDL * ROWTX));
            for (int c = 0; c < cnt; c++)
                #pragma unroll
                for (int mm = 0; mm < MDL; mm++)
                    bulk_g2s(smem0 + s * SLOTB + (c * MDL + mm) * ROWB,
                             logits + ((size_t)mm * B + base + n0 + c) * CDIM,
                             ROWTX, mb);
        };

        if (tid == 0) {
            int pre = NI < NSTAGE ? NI : NSTAGE;
            for (int it = 0; it < pre; it++) fill(it, it);
        }

        for (int it = 0; it < NI; it++) {
            const int s  = it % NSTAGE;
            const int ph = (it / NSTAGE) & 1;
            mbar_wait(smem_u32(&s_mbar[s]), ph);

            const int n = SPS * it + samp;       // this warp's sample (local)
            const int b = base + n;
            const char* slot = stage_mem + s * SLOTB;
            const bool valid = (n < ns);

            if (valid) {
                const float4* __restrict__ row =
                    (const float4*)(slot + (samp * MDL + mdl) * ROWB);

                // Winner score (ce-ent) = mean(x) - x_t + logC: logsumexp
                // cancels analytically, so the argmin (and the oracle rows)
                // is exp-free and exact in fp32. __expf/__logf error only
                // touches the scalar loss (abs tol ~2.7e-2).
                float ssum = 0.0f, sexp = 0.0f;
                #pragma unroll
                for (int k = 0; k < 8; k++) {
                    int i = lane + 32 * k;
                    if (i < NV4) {
                        float4 v = row[i];
                        ssum += (v.x + v.y) + (v.z + v.w);
                        sexp += (__expf(v.x) + __expf(v.y))
                              + (__expf(v.z) + __expf(v.w));
                    }
                }
                #pragma unroll
                for (int off = 16; off > 0; off >>= 1) {
                    ssum += __shfl_xor_sync(0xFFFFFFFFu, ssum, off);
                    sexp += __shfl_xor_sync(0xFFFFFFFFu, sexp, off);
                }
                if (lane == 0) {
                    int tgt    = is64 ? t32[2 * b] : t32[b];
                    float tval = ((const float*)row)[tgt];
                    float mean = ssum * (1.0f / CDIM);
                    s_score[samp][mdl] = mean - tval;        // ce - ent - logC
                    s_ent[samp][mdl]   = __logf(sexp) - mean - LOGC;
                }
            }
            __syncthreads();

            // Scalar accumulation (thread 0, both samples of this stage).
            if (tid == 0) {
                int cnt = ns - SPS * it; if (cnt > SPS) cnt = SPS;
                for (int c = 0; c < cnt; c++) {
                    float best = s_score[c][0];
                    int   win  = 0;
                    #pragma unroll
                    for (int m = 1; m < MDL; m++)
                        if (s_score[c][m] < best) { best = s_score[c][m]; win = m; }
                    if (idx_out) idx_out[base + SPS * it + c] = (float)win;
                    acc0 += (double)(best + LOGC);           // ce_win - ent_win
                    acc1 += (double)((s_ent[c][0] + s_ent[c][1])
                                   + (s_ent[c][2] + s_ent[c][3]));
                }
            }

            // Oracle copy: half-block per sample, straight from smem.
            // Redundant argmin (4 smem reads), strict <: jax first-min tie.
            if (valid && oracle) {
                float best = s_score[samp][0];
                int   win  = 0;
                #pragma unroll
                for (int m = 1; m < MDL; m++)
                    if (s_score[samp][m] < best) { best = s_score[samp][m]; win = m; }
                const float* __restrict__ src =
                    (const float*)(slot + (samp * MDL + win) * ROWB);
                float* __restrict__ dst = oracle + (size_t)b * CDIM;
                const int t = tid & 127;                     // 0..127 in half
                for (int i = t; i < CDIM; i += 128)
                    dst[i] = src[i];
            }
            __syncthreads();            // all reads of slot s done

            if (tid == 0) {
                int nx = it + NSTAGE;
                if (nx < NI) fill(s, nx);
            }
        }
    }

    // Block tail: one atomic pair + counter; last block finalizes and resets.
    if (tid == 0) {
        atomicAdd(&g_acc[0], acc0);
        atomicAdd(&g_acc[1], acc1);
        __threadfence();
        unsigned t = atomicAdd(&g_count, 1u);
        if (t == (unsigned)gridDim.x - 1u) {
            double a0 = __longlong_as_double(
                atomicExch((unsigned long long*)&g_acc[0], 0ull));
            double a1 = __longlong_as_double(
                atomicExch((unsigned long long*)&g_acc[1], 0ull));
            if (loss_out) loss_out[0] = (float)((a0 + a1) / (double)B);
            g_count = 0u;
            __threadfence();
        }
    }
}

extern "C" void kernel_launch(void* const* d_in, const int* in_sizes, int n_in,
                              void* d_out, int out_size)
{
    const float* logits = (const float*)d_in[0];
    const int*   t32    = (const int*)d_in[1];
    const int B = in_sizes[1];                 // 8192

    float* out = (float*)d_out;
    const long long bc = (long long)B * CDIM;

    // Output layout: tuple (new_loss, oracle_logits, min_index) flattened.
    float* loss_p   = nullptr;
    float* oracle_p = nullptr;
    float* idx_p    = nullptr;
    long long osz = (long long)out_size;
    if (osz >= 1 + bc + B) {                   // full tuple
        loss_p   = out;
        oracle_p = out + 1;
        idx_p    = out + 1 + bc;
    } else if (osz == bc + B) {                // (oracle, idx)
        oracle_p = out;
        idx_p    = out + bc;
    } else if (osz == bc) {                    // oracle only
        oracle_p = out;
    } else if (osz == B) {                     // idx only
        idx_p = out;
    } else {                                   // scalar loss only
        loss_p = out;
    }

    int q = (B + GRIDB - 1) / GRIDB;           // samples per block (contiguous)
    q = (q + SPS - 1) & ~(SPS - 1);            // even, whole stages
    const int dyn = NSTAGE * SLOTB;            // 96 KB

    cudaFuncSetAttribute(cmcl_pipe2,
                         cudaFuncAttributeMaxDynamicSharedMemorySize, dyn);
    cmcl_pipe2<<<GRIDB, NTHR, dyn>>>(logits, t32, loss_p, oracle_p, idx_p, B, q);
}